// round 1
// baseline (speedup 1.0000x reference)
#include <cuda_runtime.h>
#include <math.h>

// Problem: x (32,3,512,512) f32
//  1) maxpool 3x3 s2 p1 (-inf pad) -> (..,256,256) -> spatial mean -> silu -> gate (per n,c)
//  2) 5x5 s4 p1 zero-pad window sum / 25 -> (..,128,128)
//  3) out = winsum/25 * gate
//
// Kernel 1 (single pass over x): per 64x128 input tile (with 1-elem low halo in smem)
//   - computes maxpool outputs for the tile, reduces their sum -> g_partials[ch][tile]
//   - computes raw 5x5 window sums, writes them to d_out (unscaled)
// Kernel 2: per channel, sum 32 partials -> gate = silu(mean) ; out *= gate/25.

#define SMS 132          // smem row stride in floats (mult of 4 for float4 alignment)
#define NCH 96           // 32*3 channels
#define TILES 32         // 8 (row tiles of 64) x 4 (col tiles of 128)

__device__ float g_partials[NCH * TILES];

__global__ __launch_bounds__(256) void fused_pool_kernel(
    const float* __restrict__ x, float* __restrict__ out)
{
    __shared__ float sm[65 * SMS];
    __shared__ float red[32];

    const int tile = blockIdx.x;      // 0..31
    const int ch   = blockIdx.y;      // 0..95
    const int tx = tile & 3;          // col tile
    const int ty = tile >> 2;         // row tile
    const int r0 = ty * 64;
    const int c0 = tx * 128;
    const int tid = threadIdx.x;

    const float* __restrict__ xc = x + (size_t)ch * (512 * 512);

    // ---- load 65x129 input tile (halo at row/col -1; OOB -> 0) ----
    for (int idx = tid; idx < 65 * 129; idx += 256) {
        int r = idx / 129;
        int c = idx - r * 129;
        int gr = r0 - 1 + r;
        int gc = c0 - 1 + c;
        float v = 0.0f;
        if (gr >= 0 && gc >= 0) v = xc[gr * 512 + gc];
        sm[r * SMS + c] = v;
    }
    __syncthreads();

    // ---- maxpool 3x3 s2: 32 rows x 64 cols of outputs in this tile ----
    // thread -> output row i = tid>>3 (0..31), 8 consecutive output cols j0..j0+7
    float lsum = 0.0f;
    {
        const int i  = tid >> 3;
        const int j0 = (tid & 7) * 8;
        const int dr0 = (r0 == 0 && i == 0) ? 1 : 0;   // exclude global row -1 (pad=-inf)
        float cm[17];
        #pragma unroll
        for (int q = 0; q < 17; q++) cm[q] = -INFINITY;
        #pragma unroll
        for (int dr = 0; dr <= 2; ++dr) {
            if (dr < dr0) continue;
            const float* rowp = &sm[(2 * i + dr) * SMS + 2 * j0];
            const float4* p4 = (const float4*)rowp;
            #pragma unroll
            for (int q = 0; q < 4; q++) {
                float4 v = p4[q];
                cm[4*q+0] = fmaxf(cm[4*q+0], v.x);
                cm[4*q+1] = fmaxf(cm[4*q+1], v.y);
                cm[4*q+2] = fmaxf(cm[4*q+2], v.z);
                cm[4*q+3] = fmaxf(cm[4*q+3], v.w);
            }
            cm[16] = fmaxf(cm[16], rowp[16]);
        }
        #pragma unroll
        for (int t = 0; t < 8; t++) {
            float m;
            if (c0 == 0 && (j0 + t) == 0) {
                // exclude global col -1 (pad=-inf)
                m = fmaxf(cm[1], cm[2]);
            } else {
                m = fmaxf(fmaxf(cm[2*t], cm[2*t+1]), cm[2*t+2]);
            }
            lsum += m;
        }
    }
    // block reduction of maxpool sum (deterministic tree)
    #pragma unroll
    for (int o = 16; o > 0; o >>= 1)
        lsum += __shfl_down_sync(0xffffffffu, lsum, o);
    if ((tid & 31) == 0) red[tid >> 5] = lsum;
    __syncthreads();
    if (tid < 8) {
        float s = red[tid];
        s += __shfl_down_sync(0x000000ffu, s, 4);
        s += __shfl_down_sync(0x000000ffu, s, 2);
        s += __shfl_down_sync(0x000000ffu, s, 1);
        if (tid == 0) g_partials[ch * TILES + tile] = s;
    }

    // ---- 5x5 s4 window sum: 16 rows x 32 cols of outputs in this tile ----
    // thread -> output row i = tid>>4 (0..15), 2 consecutive output cols j0, j0+1
    {
        const int i  = tid >> 4;
        const int j0 = (tid & 15) * 2;
        float cs[9];
        #pragma unroll
        for (int q = 0; q < 9; q++) cs[q] = 0.0f;
        #pragma unroll
        for (int dr = 0; dr < 5; ++dr) {
            const float* rowp = &sm[(4 * i + dr) * SMS + 4 * j0];
            const float4* p4 = (const float4*)rowp;
            float4 a = p4[0];
            float4 b = p4[1];
            cs[0] += a.x; cs[1] += a.y; cs[2] += a.z; cs[3] += a.w;
            cs[4] += b.x; cs[5] += b.y; cs[6] += b.z; cs[7] += b.w;
            cs[8] += rowp[8];
        }
        float s0 = cs[0] + cs[1] + cs[2] + cs[3] + cs[4];
        float s1 = cs[4] + cs[5] + cs[6] + cs[7] + cs[8];
        const int oy = ty * 16 + i;
        const int ox = tx * 32 + j0;
        float2 st = make_float2(s0, s1);
        *(float2*)(&out[((size_t)ch * 128 + oy) * 128 + ox]) = st;
    }
}

// gate + scale: out *= silu(mean(maxpool)) / 25
__global__ __launch_bounds__(256) void gate_scale_kernel(float* __restrict__ out)
{
    __shared__ float gsh;
    const int ch   = blockIdx.x >> 2;   // 0..95
    const int part = blockIdx.x & 3;    // 0..3
    if (threadIdx.x == 0) {
        float s = 0.0f;
        #pragma unroll
        for (int q = 0; q < TILES; q++) s += g_partials[ch * TILES + q];
        float m = s * (1.0f / 65536.0f);         // mean over 256x256 pooled
        float g = m / (1.0f + expf(-m));         // silu
        gsh = g * (1.0f / 25.0f);                // fold the /K^2
    }
    __syncthreads();
    const float g = gsh;
    float4* p = (float4*)(out + (size_t)ch * 16384 + part * 4096);
    const int tid = threadIdx.x;
    #pragma unroll
    for (int q = 0; q < 4; q++) {
        float4 v = p[tid + q * 256];
        v.x *= g; v.y *= g; v.z *= g; v.w *= g;
        p[tid + q * 256] = v;
    }
}

extern "C" void kernel_launch(void* const* d_in, const int* in_sizes, int n_in,
                              void* d_out, int out_size)
{
    const float* x = (const float*)d_in[0];
    float* out = (float*)d_out;

    dim3 grid1(TILES, NCH);
    fused_pool_kernel<<<grid1, 256>>>(x, out);
    gate_scale_kernel<<<NCH * 4, 256>>>(out);
}

// round 2
// speedup vs baseline: 2.4198x; 2.4198x over previous
#include <cuda_runtime.h>
#include <math.h>

// x (32,3,512,512) f32
//  branch A: maxpool 3x3 s2 p1 (-inf pad) -> mean over 256x256 -> silu -> gate[ch]
//  branch B: 5x5 s4 p1 zero-pad window sum -> out (128x128), then out *= gate/25
//
// Kernel 1: register-streaming. Warp = 8-row x 128-col strip. Per row: one
//   coalesced LDG.128 per lane (4 cols/lane) + lane0 scalar halo load.
//   Streams both the 3x3/s2 max rows and 5x5/s4 sum rows via overlap-reseed.
// Kernel 2: per-channel gate = silu(mean)/25 from 256 partials.
// Kernel 3: out *= gate (streaming multiply, out is L2-resident).

#define NCH 96
#define STRIPS 64     // 512 rows / 8
#define QCOLS 4       // 4 warps cover the 512-col row

__device__ float g_partials[NCH * STRIPS * QCOLS];
__device__ float g_gate[NCH];

__global__ __launch_bounds__(256) void fused_pool_kernel(
    const float* __restrict__ x, float* __restrict__ out)
{
    const int tid  = threadIdx.x;
    const int lane = tid & 31;
    const int warp = tid >> 5;

    // block covers 2 strips: warps 0..3 -> strip A (quarters 0..3), warps 4..7 -> strip B
    const int ch    = blockIdx.x >> 5;            // 96 channels, grid = 96*32
    const int spair = blockIdx.x & 31;            // 0..31
    const int s     = spair * 2 + (warp >> 2);    // strip 0..63 (8 input rows each)
    const int qc    = warp & 3;                   // column quarter
    const int base  = qc * 128;                   // first col of quarter

    const float* __restrict__ xc = x + (size_t)ch * 262144;
    const int col0 = base + lane * 4;

    // per-lane accumulators over its 4 columns
    float ws0 = 0.f, ws1 = 0.f, ws2 = 0.f, ws3 = 0.f;                    // window col sums
    float wm0 = -INFINITY, wm1 = -INFINITY, wm2 = -INFINITY, wm3 = -INFINITY; // max col maxes
    float hsum = 0.f, hmax = -INFINITY;   // halo col (base-1), meaningful on lane 0 only
    float lsum = 0.f;                     // gate partial (sum of maxpool outputs)

    #pragma unroll
    for (int q = 0; q <= 8; ++q) {
        const int gr = 8 * s - 1 + q;                 // global input row
        float r0 = 0.f, r1 = 0.f, r2 = 0.f, r3 = 0.f, hv = 0.f;
        const bool rowvalid = (q > 0) || (s > 0);     // s==0,q==0 is the -1 pad row

        if (rowvalid) {
            const float4 v = *(const float4*)(xc + (size_t)gr * 512 + col0);
            r0 = v.x; r1 = v.y; r2 = v.z; r3 = v.w;
            if (lane == 0 && qc > 0) hv = xc[(size_t)gr * 512 + base - 1];
        }

        // window sums: zero-pad identity, always add
        ws0 += r0; ws1 += r1; ws2 += r2; ws3 += r3; hsum += hv;
        // maxpool: exclude pad row
        if (rowvalid) {
            wm0 = fmaxf(wm0, r0); wm1 = fmaxf(wm1, r1);
            wm2 = fmaxf(wm2, r2); wm3 = fmaxf(wm3, r3);
            if (qc > 0) hmax = fmaxf(hmax, hv);
        }

        // finalize maxpool row my = 4s + q/2 - 1 at q = 2,4,6,8
        if (q == 2 || q == 4 || q == 6 || q == 8) {
            float left = __shfl_up_sync(0xffffffffu, wm3, 1);
            if (lane == 0) left = hmax;               // col base-1 (pad -inf if qc==0)
            float ma = fmaxf(fmaxf(left, wm0), wm1);  // output col 64qc+2L
            float mb = fmaxf(fmaxf(wm1, wm2), wm3);   // output col 64qc+2L+1
            lsum += ma + mb;
            if (q < 8) {                              // reseed with overlap row
                wm0 = r0; wm1 = r1; wm2 = r2; wm3 = r3;
                hmax = (qc > 0) ? hv : -INFINITY;
            }
        }

        // finalize window row oy = 2s (+1) at q = 4, 8
        if (q == 4 || q == 8) {
            float left = __shfl_up_sync(0xffffffffu, ws3, 1);
            if (lane == 0) left = hsum;               // col base-1 (0 pad if qc==0)
            float w = left + ws0 + ws1 + ws2 + ws3;
            const int oy = 2 * s + (q >> 3);
            out[((size_t)ch * 128 + oy) * 128 + qc * 32 + lane] = w;
            if (q == 4) {                             // reseed with overlap row
                ws0 = r0; ws1 = r1; ws2 = r2; ws3 = r3;
                hsum = hv;
            }
        }
    }

    // warp-reduce gate partial (deterministic)
    #pragma unroll
    for (int o = 16; o > 0; o >>= 1)
        lsum += __shfl_down_sync(0xffffffffu, lsum, o);
    if (lane == 0)
        g_partials[(ch * STRIPS + s) * QCOLS + qc] = lsum;
}

// 96 blocks x 256 threads: sum the 256 partials of one channel -> silu(mean)/25
__global__ __launch_bounds__(256) void gate_kernel()
{
    __shared__ float sm[8];
    const int ch  = blockIdx.x;
    const int tid = threadIdx.x;
    float v = g_partials[ch * 256 + tid];
    #pragma unroll
    for (int o = 16; o > 0; o >>= 1)
        v += __shfl_down_sync(0xffffffffu, v, o);
    if ((tid & 31) == 0) sm[tid >> 5] = v;
    __syncthreads();
    if (tid == 0) {
        float s = 0.f;
        #pragma unroll
        for (int i = 0; i < 8; ++i) s += sm[i];
        float m = s * (1.0f / 65536.0f);            // mean over 256x256 pooled
        g_gate[ch] = (m / (1.0f + expf(-m))) * (1.0f / 25.0f);
    }
}

// out *= gate[ch]; 1536 blocks x 256 threads, exactly one float4 per thread
__global__ __launch_bounds__(256) void scale_kernel(float* __restrict__ out)
{
    const int idx = blockIdx.x * 256 + threadIdx.x;   // float4 index, 393216 total
    const int ch  = idx >> 12;                        // 4096 float4 per channel
    const float g = g_gate[ch];
    float4* p = (float4*)out;
    float4 v = p[idx];
    v.x *= g; v.y *= g; v.z *= g; v.w *= g;
    p[idx] = v;
}

extern "C" void kernel_launch(void* const* d_in, const int* in_sizes, int n_in,
                              void* d_out, int out_size)
{
    const float* x = (const float*)d_in[0];
    float* out = (float*)d_out;

    fused_pool_kernel<<<NCH * 32, 256>>>(x, out);
    gate_kernel<<<NCH, 256>>>();
    scale_kernel<<<1536, 256>>>(out);
}

// round 7
// speedup vs baseline: 2.9100x; 1.2026x over previous
#include <cuda_runtime.h>
#include <math.h>

// x (32,3,512,512) f32
//  branch A: maxpool 3x3 s2 p1 (-inf pad) -> mean over 256x256 -> silu -> gate[ch]
//  branch B: 5x5 s4 p1 zero-pad window sum -> out (128x128), then out *= gate/25
//
// Kernel 1: register-streaming, warp = 16-row x 128-col strip, prefetch-next-row
//   pipeline. One coalesced LDG.128 per lane per row + lane0 scalar halo.
// Kernel 2: fused gate+scale: block reduces its channel's 128 partials -> gate,
//   then scales its quarter of out (L2-resident).

#define NCH 96
#define STRIPS 32     // 512 rows / 16

__device__ float g_partials[NCH * STRIPS * 4];

__global__ __launch_bounds__(256) void fused_pool_kernel(
    const float* __restrict__ x, float* __restrict__ out)
{
    const int tid  = threadIdx.x;
    const int lane = tid & 31;
    const int warp = tid >> 5;

    // block = 2 strips x 4 column-quarters; grid = 96 * 16
    const int ch   = blockIdx.x >> 4;
    const int grp  = blockIdx.x & 15;
    const int s    = grp * 2 + (warp >> 2);   // strip 0..31 (16 input rows)
    const int qc   = warp & 3;                // column quarter
    const int base = qc * 128;

    const float* __restrict__ xc = x + (size_t)ch * 262144;
    const float* __restrict__ rp = xc + base + lane * 4;   // lane's float4 column
    const float* __restrict__ hp = xc + base - 1;          // halo column
    const int r0 = 16 * s - 1;                             // row of q=0

    float ws0 = 0.f, ws1 = 0.f, ws2 = 0.f, ws3 = 0.f;
    float wm0 = -INFINITY, wm1 = -INFINITY, wm2 = -INFINITY, wm3 = -INFINITY;
    float hsum = 0.f, hmax = -INFINITY;
    float lsum = 0.f;

    const bool do_halo = (lane == 0) && (qc > 0);

    // prime q=0 (row 16s-1; pad row when s==0)
    float4 cur; float hcur;
    if (s > 0) {
        cur = *(const float4*)(rp + (size_t)r0 * 512);
        hcur = do_halo ? hp[(size_t)r0 * 512] : 0.f;
    } else {
        cur = make_float4(0.f, 0.f, 0.f, 0.f);
        hcur = 0.f;
    }

    #pragma unroll
    for (int q = 0; q <= 16; ++q) {
        // prefetch next row (q+1 >= 1 is always a valid image row)
        float4 nxt; float hnxt = 0.f;
        if (q < 16) {
            nxt = *(const float4*)(rp + (size_t)(r0 + q + 1) * 512);
            if (do_halo) hnxt = hp[(size_t)(r0 + q + 1) * 512];
        }

        // window sums (zero pad: always add)
        ws0 += cur.x; ws1 += cur.y; ws2 += cur.z; ws3 += cur.w; hsum += hcur;
        // max (exclude the -inf pad row at s==0,q==0)
        if (q > 0 || s > 0) {
            wm0 = fmaxf(wm0, cur.x); wm1 = fmaxf(wm1, cur.y);
            wm2 = fmaxf(wm2, cur.z); wm3 = fmaxf(wm3, cur.w);
            if (qc > 0) hmax = fmaxf(hmax, hcur);
        }

        // finalize maxpool row my = 8s + q/2 - 1 at even q >= 2
        if (q >= 2 && (q & 1) == 0) {
            float left = __shfl_up_sync(0xffffffffu, wm3, 1);
            if (lane == 0) left = hmax;               // -inf for qc==0 (col pad)
            float ma = fmaxf(fmaxf(left, wm0), wm1);
            float mb = fmaxf(fmaxf(wm1, wm2), wm3);
            lsum += ma + mb;
            if (q < 16) {                             // reseed with overlap row
                wm0 = cur.x; wm1 = cur.y; wm2 = cur.z; wm3 = cur.w;
                hmax = (qc > 0) ? hcur : -INFINITY;
            }
        }

        // finalize window row oy = 4s + q/4 - 1 at q = 4,8,12,16
        if (q >= 4 && (q & 3) == 0) {
            float left = __shfl_up_sync(0xffffffffu, ws3, 1);
            if (lane == 0) left = hsum;               // 0 for qc==0 (zero pad)
            float w = left + ws0 + ws1 + ws2 + ws3;
            const int oy = 4 * s + (q >> 2) - 1;
            out[((size_t)ch * 128 + oy) * 128 + qc * 32 + lane] = w;
            if (q == 4 || q == 8 || q == 12) {        // reseed with overlap row
                ws0 = cur.x; ws1 = cur.y; ws2 = cur.z; ws3 = cur.w;
                hsum = hcur;
            }
        }

        cur = nxt; hcur = hnxt;
    }

    // warp-reduce gate partial (deterministic)
    #pragma unroll
    for (int o = 16; o > 0; o >>= 1)
        lsum += __shfl_down_sync(0xffffffffu, lsum, o);
    if (lane == 0)
        g_partials[(ch * STRIPS + s) * 4 + qc] = lsum;
}

// fused gate + scale: 384 blocks (96 ch x 4 quarters), 256 threads
__global__ __launch_bounds__(256) void gate_scale_kernel(float* __restrict__ out)
{
    __shared__ float sred[8];
    __shared__ float gsh;
    const int ch   = blockIdx.x >> 2;
    const int part = blockIdx.x & 3;
    const int tid  = threadIdx.x;

    // reduce 128 partials of this channel (threads 128..255 contribute 0)
    float v = (tid < 128) ? g_partials[ch * 128 + tid] : 0.f;
    #pragma unroll
    for (int o = 16; o > 0; o >>= 1)
        v += __shfl_down_sync(0xffffffffu, v, o);
    if ((tid & 31) == 0) sred[tid >> 5] = v;
    __syncthreads();
    if (tid == 0) {
        float s = sred[0] + sred[1] + sred[2] + sred[3];
        float m = s * (1.0f / 65536.0f);              // mean over 256x256 pooled
        gsh = (m / (1.0f + expf(-m))) * (1.0f / 25.0f);
    }
    __syncthreads();
    const float g = gsh;

    float4* p = (float4*)out + (size_t)ch * 4096 + part * 1024;
    #pragma unroll
    for (int i = 0; i < 4; ++i) {
        float4 v4 = p[tid + i * 256];
        v4.x *= g; v4.y *= g; v4.z *= g; v4.w *= g;
        p[tid + i * 256] = v4;
    }
}

extern "C" void kernel_launch(void* const* d_in, const int* in_sizes, int n_in,
                              void* d_out, int out_size)
{
    const float* x = (const float*)d_in[0];
    float* out = (float*)d_out;

    fused_pool_kernel<<<NCH * 16, 256>>>(x, out);
    gate_scale_kernel<<<NCH * 4, 256>>>(out);
}

// round 8
// speedup vs baseline: 3.0626x; 1.0525x over previous
#include <cuda_runtime.h>
#include <math.h>

// x (32,3,512,512) f32
//  branch A: maxpool 3x3 s2 p1 (-inf pad) -> mean over 256x256 -> silu -> gate[ch]
//  branch B: 5x5 s4 p1 zero-pad window sum -> out (128x128), then out *= gate/25
//
// Kernel 1: register-streaming. Warp = 16-row x 256-col strip; each lane owns 8
//   contiguous cols (two float4 loads per row), depth-2 row prefetch, 1 scalar
//   halo load per row per 512 cols (lane0 of the h==1 warp only).
// Kernel 2: fused gate+scale: block reduces its channel's 64 partials -> gate,
//   then scales its quarter of out (L2-resident).

#define NCH 96
#define STRIPS 32     // 512 rows / 16

__device__ float g_partials[NCH * STRIPS * 2];

__global__ __launch_bounds__(256, 4) void fused_pool_kernel(
    const float* __restrict__ x, float* __restrict__ out)
{
    const int tid  = threadIdx.x;
    const int lane = tid & 31;
    const int warp = tid >> 5;

    // block = 4 strips x 2 halves; grid = 96 * 8
    const int ch   = blockIdx.x >> 3;
    const int grp  = blockIdx.x & 7;
    const int s    = grp * 4 + (warp >> 1);   // strip 0..31 (16 input rows)
    const int h    = warp & 1;                // column half (256 cols)
    const int base = h * 256;

    const float* __restrict__ xc = x + (size_t)ch * 262144;
    const float* __restrict__ rp = xc + base + lane * 8;   // lane's 8-col segment
    const float* __restrict__ hp = xc + 255;               // halo col (h==1 only)
    const int r0 = 16 * s - 1;                             // row of q=0

    // accumulators: a = cols c0..c0+3, b = cols c0+4..c0+7
    float wsa0=0.f, wsa1=0.f, wsa2=0.f, wsa3=0.f;
    float wsb0=0.f, wsb1=0.f, wsb2=0.f, wsb3=0.f;
    float wma0=-INFINITY, wma1=-INFINITY, wma2=-INFINITY, wma3=-INFINITY;
    float wmb0=-INFINITY, wmb1=-INFINITY, wmb2=-INFINITY, wmb3=-INFINITY;
    float hsum = 0.f, hmax = -INFINITY;
    float lsum = 0.f;

    const bool do_halo = (lane == 0) && (h == 1);

    // prime q=0 (row 16s-1; pad row when s==0)
    float4 curA, curB; float hcur;
    if (s > 0) {
        curA = *(const float4*)(rp + (size_t)r0 * 512);
        curB = *(const float4*)(rp + (size_t)r0 * 512 + 4);
        hcur = do_halo ? hp[(size_t)r0 * 512] : 0.f;
    } else {
        curA = make_float4(0.f, 0.f, 0.f, 0.f);
        curB = curA;
        hcur = 0.f;
    }

    #pragma unroll
    for (int q = 0; q <= 16; ++q) {
        // prefetch next row (r0+q+1 >= 16s is always a valid image row)
        float4 nxtA, nxtB; float hnxt = 0.f;
        if (q < 16) {
            const size_t ro = (size_t)(r0 + q + 1) * 512;
            nxtA = *(const float4*)(rp + ro);
            nxtB = *(const float4*)(rp + ro + 4);
            if (do_halo) hnxt = hp[ro];
        }

        // window sums (zero pad: always add)
        wsa0 += curA.x; wsa1 += curA.y; wsa2 += curA.z; wsa3 += curA.w;
        wsb0 += curB.x; wsb1 += curB.y; wsb2 += curB.z; wsb3 += curB.w;
        hsum += hcur;
        // max (exclude the -inf pad row at s==0,q==0)
        if (q > 0 || s > 0) {
            wma0 = fmaxf(wma0, curA.x); wma1 = fmaxf(wma1, curA.y);
            wma2 = fmaxf(wma2, curA.z); wma3 = fmaxf(wma3, curA.w);
            wmb0 = fmaxf(wmb0, curB.x); wmb1 = fmaxf(wmb1, curB.y);
            wmb2 = fmaxf(wmb2, curB.z); wmb3 = fmaxf(wmb3, curB.w);
            if (h == 1) hmax = fmaxf(hmax, hcur);
        }

        // finalize maxpool row my = 8s + q/2 - 1 at even q >= 2
        if (q >= 2 && (q & 1) == 0) {
            float left = __shfl_up_sync(0xffffffffu, wmb3, 1);
            if (lane == 0) left = (h == 1) ? hmax : -INFINITY;  // col pad at h==0
            float m0 = fmaxf(fmaxf(left, wma0), wma1);          // out col c0
            float m1 = fmaxf(fmaxf(wma1, wma2), wma3);          // out col c0+2
            float m2 = fmaxf(fmaxf(wma3, wmb0), wmb1);          // out col c0+4
            float m3 = fmaxf(fmaxf(wmb1, wmb2), wmb3);          // out col c0+6
            lsum += (m0 + m1) + (m2 + m3);
            if (q < 16) {                              // reseed with overlap row
                wma0 = curA.x; wma1 = curA.y; wma2 = curA.z; wma3 = curA.w;
                wmb0 = curB.x; wmb1 = curB.y; wmb2 = curB.z; wmb3 = curB.w;
                hmax = (h == 1) ? hcur : -INFINITY;
            }
        }

        // finalize window row oy = 4s + q/4 - 1 at q = 4,8,12,16
        if (q >= 4 && (q & 3) == 0) {
            float left = __shfl_up_sync(0xffffffffu, wsb3, 1);
            if (lane == 0) left = (h == 1) ? hsum : 0.f;        // zero pad at h==0
            float w0 = left + wsa0 + wsa1 + wsa2 + wsa3;        // out col c0
            float w1 = wsa3 + wsb0 + wsb1 + wsb2 + wsb3;        // out col c0+4
            const int oy = 4 * s + (q >> 2) - 1;
            const int ox = h * 64 + lane * 2;
            *(float2*)(&out[((size_t)ch * 128 + oy) * 128 + ox]) = make_float2(w0, w1);
            if (q < 16) {                              // reseed with overlap row
                wsa0 = curA.x; wsa1 = curA.y; wsa2 = curA.z; wsa3 = curA.w;
                wsb0 = curB.x; wsb1 = curB.y; wsb2 = curB.z; wsb3 = curB.w;
                hsum = hcur;
            }
        }

        curA = nxtA; curB = nxtB; hcur = hnxt;
    }

    // warp-reduce gate partial (deterministic)
    #pragma unroll
    for (int o = 16; o > 0; o >>= 1)
        lsum += __shfl_down_sync(0xffffffffu, lsum, o);
    if (lane == 0)
        g_partials[(ch * STRIPS + s) * 2 + h] = lsum;
}

// fused gate + scale: 384 blocks (96 ch x 4 quarters), 256 threads
__global__ __launch_bounds__(256) void gate_scale_kernel(float* __restrict__ out)
{
    __shared__ float sred[2];
    __shared__ float gsh;
    const int ch   = blockIdx.x >> 2;
    const int part = blockIdx.x & 3;
    const int tid  = threadIdx.x;

    // reduce 64 partials of this channel (threads 64..255 contribute 0)
    float v = (tid < 64) ? g_partials[ch * 64 + tid] : 0.f;
    #pragma unroll
    for (int o = 16; o > 0; o >>= 1)
        v += __shfl_down_sync(0xffffffffu, v, o);
    if (tid < 64 && (tid & 31) == 0) sred[tid >> 5] = v;
    __syncthreads();
    if (tid == 0) {
        float ssum = sred[0] + sred[1];
        float m = ssum * (1.0f / 65536.0f);           // mean over 256x256 pooled
        gsh = (m / (1.0f + expf(-m))) * (1.0f / 25.0f);
    }
    __syncthreads();
    const float g = gsh;

    float4* p = (float4*)out + (size_t)ch * 4096 + part * 1024;
    #pragma unroll
    for (int i = 0; i < 4; ++i) {
        float4 v4 = p[tid + i * 256];
        v4.x *= g; v4.y *= g; v4.z *= g; v4.w *= g;
        p[tid + i * 256] = v4;
    }
}

extern "C" void kernel_launch(void* const* d_in, const int* in_sizes, int n_in,
                              void* d_out, int out_size)
{
    const float* x = (const float*)d_in[0];
    float* out = (float*)d_out;

    fused_pool_kernel<<<NCH * 8, 256>>>(x, out);
    gate_scale_kernel<<<NCH * 4, 256>>>(out);
}